// round 2
// baseline (speedup 1.0000x reference)
#include <cuda_runtime.h>
#include <cstdint>

#define S_LEN 4096
#define B_SZ 4
#define HID 512
#define CTX_ELEMS (B_SZ * S_LEN * HID)   // 8388608 floats

// Scratch for projected Q, K, V (device globals: no allocation allowed)
__device__ float g_Q[CTX_ELEMS];
__device__ float g_K[CTX_ELEMS];
__device__ float g_V[CTX_ELEMS];

// Smem tile pitch (floats). 36 => bank = (36*r + c) % 32 = (4r + c) % 32,
// conflict-free for the frag-load pattern r in [0,8), c in [0,4).
#define PITCH 36
#define TILE_F (128 * PITCH)             // floats per 128x32 tile buffer
#define SMEM_BYTES (4 * TILE_F * 4)      // As0,As1,Bs0,Bs1 = 73728 B

// ---------------------------------------------------------------------------
// TF32 / cp.async helpers
// ---------------------------------------------------------------------------
__device__ __forceinline__ uint32_t f2tf32(float x) {
    uint32_t y;
    asm("cvt.rna.tf32.f32 %0, %1;" : "=r"(y) : "f"(x));
    return y;
}

__device__ __forceinline__ void mma_tf32(float d[4], const uint32_t a[4], const uint32_t b[2]) {
    asm volatile(
        "mma.sync.aligned.m16n8k8.row.col.f32.tf32.tf32.f32 "
        "{%0,%1,%2,%3}, {%4,%5,%6,%7}, {%8,%9}, {%0,%1,%2,%3};\n"
        : "+f"(d[0]), "+f"(d[1]), "+f"(d[2]), "+f"(d[3])
        : "r"(a[0]), "r"(a[1]), "r"(a[2]), "r"(a[3]),
          "r"(b[0]), "r"(b[1]));
}

__device__ __forceinline__ void cp16(float* smem_dst, const float* gsrc) {
    uint32_t s = (uint32_t)__cvta_generic_to_shared(smem_dst);
    asm volatile("cp.async.cg.shared.global [%0], [%1], 16;\n" :: "r"(s), "l"(gsrc));
}
#define CP_COMMIT() asm volatile("cp.async.commit_group;\n" ::: "memory")
#define CP_WAIT1()  asm volatile("cp.async.wait_group 1;\n" ::: "memory")
#define CP_WAIT0()  asm volatile("cp.async.wait_group 0;\n" ::: "memory")

// ---------------------------------------------------------------------------
// Shared GEMM tile compute: C(128x128) += A(128x32) * B(128x32)^T
// As/Bs hold raw fp32, layout [row][k] pitch PITCH; cvt to tf32 at frag load.
// 8 warps: wm in [0,4) (32 rows each), wn in [0,2) (64 cols each).
// ---------------------------------------------------------------------------
__device__ __forceinline__ void tile_mma(const float* As, const float* Bs,
                                         float acc[2][8][4], int lane, int wm, int wn) {
    const int g = lane >> 2;
    const int t = lane & 3;
#pragma unroll
    for (int kk = 0; kk < 32; kk += 8) {
        uint32_t a[2][4], b[8][2];
#pragma unroll
        for (int i = 0; i < 2; i++) {
            int r = wm * 32 + i * 16 + g;
            a[i][0] = f2tf32(As[r * PITCH + kk + t]);
            a[i][1] = f2tf32(As[(r + 8) * PITCH + kk + t]);
            a[i][2] = f2tf32(As[r * PITCH + kk + t + 4]);
            a[i][3] = f2tf32(As[(r + 8) * PITCH + kk + t + 4]);
        }
#pragma unroll
        for (int j = 0; j < 8; j++) {
            int n = wn * 64 + j * 8 + g;
            b[j][0] = f2tf32(Bs[n * PITCH + kk + t]);
            b[j][1] = f2tf32(Bs[n * PITCH + kk + t + 4]);
        }
#pragma unroll
        for (int i = 0; i < 2; i++)
#pragma unroll
            for (int j = 0; j < 8; j++)
                mma_tf32(acc[i][j], a[i], b[j]);
    }
}

// Async-load a 128x32 fp32 tile (row-major, K-contiguous, g at row0/col0).
// 256 threads, 4x cp.async(16B) each.
__device__ __forceinline__ void load_nt_async(float* S, const float* g, int ld, int tid) {
    int r = tid >> 3;           // 0..31
    int c = (tid & 7) * 4;      // 0,4,...,28
#pragma unroll
    for (int rr = 0; rr < 128; rr += 32)
        cp16(S + (r + rr) * PITCH + c, g + (size_t)(r + rr) * ld + c);
}

// Accumulator element coordinates inside the 128x128 CTA tile.
#define ACC_ROW(wm, i, lane, q) ((wm) * 32 + (i) * 16 + ((lane) >> 2) + (((q) >> 1) * 8))
#define ACC_COL(wn, j, lane, q) ((wn) * 64 + (j) * 8 + ((lane) & 3) * 2 + ((q) & 1))

#define ACC_INIT()                                 \
    float acc[2][8][4];                            \
    _Pragma("unroll") for (int i = 0; i < 2; i++)  \
    _Pragma("unroll") for (int j = 0; j < 8; j++)  \
    _Pragma("unroll") for (int q = 0; q < 4; q++) acc[i][j][q] = 0.f;

// ---------------------------------------------------------------------------
// Kernel 1: QKV projection.  out[m,o] = sum_h X[m,h] * W[o,h] + b[o]
// grid (4, 128, 3): z selects {Q,K,V}
// ---------------------------------------------------------------------------
__global__ __launch_bounds__(256) void proj_kernel(
    const float* __restrict__ Xq, const float* __restrict__ Xk, const float* __restrict__ Xv,
    const float* __restrict__ Wq, const float* __restrict__ bq,
    const float* __restrict__ Wk, const float* __restrict__ bk,
    const float* __restrict__ Wv, const float* __restrict__ bv) {
    extern __shared__ float sm[];
    float* As_[2] = {sm, sm + TILE_F};
    float* Bs_[2] = {sm + 2 * TILE_F, sm + 3 * TILE_F};

    const int mat = blockIdx.z;
    const float* X = (mat == 0) ? Xq : (mat == 1) ? Xk : Xv;
    const float* W = (mat == 0) ? Wq : (mat == 1) ? Wk : Wv;
    const float* bias = (mat == 0) ? bq : (mat == 1) ? bk : bv;
    float* out = (mat == 0) ? g_Q : (mat == 1) ? g_K : g_V;

    const int m0 = blockIdx.y * 128;
    const int n0 = blockIdx.x * 128;
    const int tid = threadIdx.x;
    const int lane = tid & 31;
    const int warp = tid >> 5;
    const int wm = warp & 3;
    const int wn = warp >> 2;

    ACC_INIT();

    const float* Ab = X + (size_t)m0 * HID;
    const float* Bb = W + (size_t)n0 * HID;
    const int ntiles = HID / 32;  // 16

    load_nt_async(As_[0], Ab, HID, tid);
    load_nt_async(Bs_[0], Bb, HID, tid);
    CP_COMMIT();

    for (int kt = 0; kt < ntiles; kt++) {
        const int cur = kt & 1, nxt = cur ^ 1;
        if (kt + 1 < ntiles) {
            load_nt_async(As_[nxt], Ab + (kt + 1) * 32, HID, tid);
            load_nt_async(Bs_[nxt], Bb + (kt + 1) * 32, HID, tid);
            CP_COMMIT();
            CP_WAIT1();
        } else {
            CP_WAIT0();
        }
        __syncthreads();
        tile_mma(As_[cur], Bs_[cur], acc, lane, wm, wn);
        __syncthreads();
    }

#pragma unroll
    for (int i = 0; i < 2; i++)
#pragma unroll
        for (int j = 0; j < 8; j++)
#pragma unroll
            for (int q = 0; q < 4; q++) {
                int rl = ACC_ROW(wm, i, lane, q);
                int cl = ACC_COL(wn, j, lane, q);
                out[(size_t)(m0 + rl) * HID + n0 + cl] = acc[i][j][q] + bias[n0 + cl];
            }
}

// ---------------------------------------------------------------------------
// Kernel 2: scores = scale * Q K^T, causal. Raw scores in the lower triangle,
// exact 0 above the diagonal (softmax of -1e7 underflows to exactly 0, and
// kernel 3 never reads cols > row).
// grid (32, 32, 4)
// ---------------------------------------------------------------------------
__global__ __launch_bounds__(256) void scores_kernel(float* __restrict__ wts) {
    extern __shared__ float sm[];
    float* As_[2] = {sm, sm + TILE_F};
    float* Bs_[2] = {sm + 2 * TILE_F, sm + 3 * TILE_F};

    const int b = blockIdx.z;
    const int m0 = blockIdx.y * 128;
    const int n0 = blockIdx.x * 128;
    const int tid = threadIdx.x;
    float* wb = wts + (size_t)b * S_LEN * S_LEN;

    if (n0 > m0) {  // strictly above diagonal: zero fill and exit
        float4 z = make_float4(0.f, 0.f, 0.f, 0.f);
        int rr = tid >> 5;            // 0..7
        int c4 = (tid & 31) * 4;      // 0..124
#pragma unroll
        for (int s = 0; s < 128; s += 8)
            *(float4*)(wb + (size_t)(m0 + rr + s) * S_LEN + n0 + c4) = z;
        return;
    }

    const int lane = tid & 31;
    const int warp = tid >> 5;
    const int wm = warp & 3;
    const int wn = warp >> 2;
    const float* Ab = g_Q + (size_t)b * S_LEN * HID + (size_t)m0 * HID;
    const float* Bb = g_K + (size_t)b * S_LEN * HID + (size_t)n0 * HID;

    ACC_INIT();

    const int ntiles = HID / 32;
    load_nt_async(As_[0], Ab, HID, tid);
    load_nt_async(Bs_[0], Bb, HID, tid);
    CP_COMMIT();

    for (int kt = 0; kt < ntiles; kt++) {
        const int cur = kt & 1, nxt = cur ^ 1;
        if (kt + 1 < ntiles) {
            load_nt_async(As_[nxt], Ab + (kt + 1) * 32, HID, tid);
            load_nt_async(Bs_[nxt], Bb + (kt + 1) * 32, HID, tid);
            CP_COMMIT();
            CP_WAIT1();
        } else {
            CP_WAIT0();
        }
        __syncthreads();
        tile_mma(As_[cur], Bs_[cur], acc, lane, wm, wn);
        __syncthreads();
    }

    const float scale = 0.04419417382415922f;  // 1/sqrt(512)
#pragma unroll
    for (int i = 0; i < 2; i++)
#pragma unroll
        for (int j = 0; j < 8; j++)
#pragma unroll
            for (int q = 0; q < 4; q++) {
                int rl = ACC_ROW(wm, i, lane, q);
                int cl = ACC_COL(wn, j, lane, q);
                float v = acc[i][j][q] * scale;
                if (n0 + cl > m0 + rl) v = 0.f;  // only bites on diagonal block
                wb[(size_t)(m0 + rl) * S_LEN + n0 + cl] = v;
            }
}

// ---------------------------------------------------------------------------
// Kernel 3: in-place row softmax over cols [0, row] only.
// One block (256 threads) per row; row staged entirely in smem.
// ---------------------------------------------------------------------------
__global__ __launch_bounds__(256) void softmax_kernel(float* __restrict__ wts) {
    __shared__ float buf[S_LEN];
    __shared__ float sred[8];
    __shared__ float sbc;

    const int row = blockIdx.x;
    const int r = row & (S_LEN - 1);
    const int n = r + 1;
    float* p = wts + (size_t)row * S_LEN;
    const int tid = threadIdx.x;

    float lm = -1e30f;
    for (int i = tid; i < n; i += 256) {
        float v = p[i];
        buf[i] = v;
        lm = fmaxf(lm, v);
    }
#pragma unroll
    for (int o = 16; o; o >>= 1) lm = fmaxf(lm, __shfl_xor_sync(0xffffffffu, lm, o));
    if ((tid & 31) == 0) sred[tid >> 5] = lm;
    __syncthreads();
    if (tid < 32) {
        float x = (tid < 8) ? sred[tid] : -1e30f;
#pragma unroll
        for (int o = 4; o; o >>= 1) x = fmaxf(x, __shfl_xor_sync(0xffffffffu, x, o));
        if (tid == 0) sbc = x;
    }
    __syncthreads();
    const float mx = sbc;

    float ls = 0.f;
    for (int i = tid; i < n; i += 256) {
        float e = __expf(buf[i] - mx);
        buf[i] = e;
        ls += e;
    }
#pragma unroll
    for (int o = 16; o; o >>= 1) ls += __shfl_xor_sync(0xffffffffu, ls, o);
    if ((tid & 31) == 0) sred[tid >> 5] = ls;
    __syncthreads();
    if (tid < 32) {
        float x = (tid < 8) ? sred[tid] : 0.f;
#pragma unroll
        for (int o = 4; o; o >>= 1) x += __shfl_xor_sync(0xffffffffu, x, o);
        if (tid == 0) sbc = x;
    }
    __syncthreads();
    const float inv = 1.0f / sbc;
    for (int i = tid; i < n; i += 256) p[i] = buf[i] * inv;
}

// ---------------------------------------------------------------------------
// Kernel 4: context = A V.  A has exact zeros above the diagonal, so no
// masking: just truncate the K loop at the diagonal block.
// A tiles via cp.async; V tile needs transpose -> LDG before MMA, STS after.
// grid (4, 32, 4): x = h-chunk (128 of 512), y = q-tile, z = batch
// ---------------------------------------------------------------------------
__global__ __launch_bounds__(256) void context_kernel(const float* __restrict__ wts,
                                                      float* __restrict__ ctx) {
    extern __shared__ float sm[];
    float* As_[2] = {sm, sm + TILE_F};
    float* Bs_[2] = {sm + 2 * TILE_F, sm + 3 * TILE_F};

    const int b = blockIdx.z;
    const int m0 = blockIdx.y * 128;
    const int h0 = blockIdx.x * 128;
    const int tid = threadIdx.x;
    const int lane = tid & 31;
    const int warp = tid >> 5;
    const int wm = warp & 3;
    const int wn = warp >> 2;

    const float* Ab = wts + (size_t)b * S_LEN * S_LEN + (size_t)m0 * S_LEN;
    const float* V = g_V + (size_t)b * S_LEN * HID;

    ACC_INIT();

    const int kr = tid >> 5;        // 0..7
    const int c4 = (tid & 31) * 4;  // 0..124

    // Bs[nxt] transposed store helper pieces: each thread handles rows kr+{0,8,16,24}
    const int ntiles = m0 / 32 + 4;  // only s <= m0+127 contributes

    // Prologue: tile 0
    load_nt_async(As_[0], Ab, S_LEN, tid);
    CP_COMMIT();
    {
        const float* Vt = V + (size_t)0 * HID + h0;
#pragma unroll
        for (int ss = 0; ss < 32; ss += 8) {
            float4 v = *(const float4*)(Vt + (size_t)(kr + ss) * HID + c4);
            Bs_[0][(c4 + 0) * PITCH + kr + ss] = v.x;
            Bs_[0][(c4 + 1) * PITCH + kr + ss] = v.y;
            Bs_[0][(c4 + 2) * PITCH + kr + ss] = v.z;
            Bs_[0][(c4 + 3) * PITCH + kr + ss] = v.w;
        }
    }

    for (int kt = 0; kt < ntiles; kt++) {
        const int cur = kt & 1, nxt = cur ^ 1;
        float4 vb[4];
        const bool more = (kt + 1 < ntiles);
        if (more) {
            load_nt_async(As_[nxt], Ab + (kt + 1) * 32, S_LEN, tid);
            CP_COMMIT();
            const float* Vt = V + (size_t)(kt + 1) * 32 * HID + h0;
#pragma unroll
            for (int ss = 0; ss < 4; ss++)
                vb[ss] = *(const float4*)(Vt + (size_t)(kr + ss * 8) * HID + c4);
            CP_WAIT1();
        } else {
            CP_WAIT0();
        }
        __syncthreads();
        tile_mma(As_[cur], Bs_[cur], acc, lane, wm, wn);
        if (more) {
#pragma unroll
            for (int ss = 0; ss < 4; ss++) {
                Bs_[nxt][(c4 + 0) * PITCH + kr + ss * 8] = vb[ss].x;
                Bs_[nxt][(c4 + 1) * PITCH + kr + ss * 8] = vb[ss].y;
                Bs_[nxt][(c4 + 2) * PITCH + kr + ss * 8] = vb[ss].z;
                Bs_[nxt][(c4 + 3) * PITCH + kr + ss * 8] = vb[ss].w;
            }
        }
        __syncthreads();
    }

#pragma unroll
    for (int i = 0; i < 2; i++)
#pragma unroll
        for (int j = 0; j < 8; j++)
#pragma unroll
            for (int q = 0; q < 4; q++) {
                int rl = ACC_ROW(wm, i, lane, q);
                int cl = ACC_COL(wn, j, lane, q);
                ctx[(size_t)(b * S_LEN + m0 + rl) * HID + h0 + cl] = acc[i][j][q];
            }
}

// ---------------------------------------------------------------------------
// Launch
// ---------------------------------------------------------------------------
extern "C" void kernel_launch(void* const* d_in, const int* in_sizes, int n_in,
                              void* d_out, int out_size) {
    const float* queries = (const float*)d_in[0];
    const float* keys    = (const float*)d_in[1];
    const float* values  = (const float*)d_in[2];
    const float* Wq      = (const float*)d_in[3];
    const float* bq      = (const float*)d_in[4];
    const float* Wk      = (const float*)d_in[5];
    const float* bk      = (const float*)d_in[6];
    const float* Wv      = (const float*)d_in[7];
    const float* bv      = (const float*)d_in[8];

    float* ctx = (float*)d_out;                 // (B, S, H)
    float* wts = (float*)d_out + CTX_ELEMS;     // (B, S, S)

    // Idempotent attribute sets (not stream ops; capture-safe).
    cudaFuncSetAttribute(proj_kernel,    cudaFuncAttributeMaxDynamicSharedMemorySize, SMEM_BYTES);
    cudaFuncSetAttribute(scores_kernel,  cudaFuncAttributeMaxDynamicSharedMemorySize, SMEM_BYTES);
    cudaFuncSetAttribute(context_kernel, cudaFuncAttributeMaxDynamicSharedMemorySize, SMEM_BYTES);

    proj_kernel<<<dim3(4, 128, 3), 256, SMEM_BYTES>>>(queries, keys, values, Wq, bq, Wk, bk, Wv, bv);
    scores_kernel<<<dim3(32, 32, 4), 256, SMEM_BYTES>>>(wts);
    softmax_kernel<<<B_SZ * S_LEN, 256>>>(wts);
    context_kernel<<<dim3(4, 32, 4), 256, SMEM_BYTES>>>(wts, ctx);
}

// round 5
// speedup vs baseline: 1.3554x; 1.3554x over previous
#include <cuda_runtime.h>
#include <cstdint>

#define S_LEN 4096
#define B_SZ 4
#define HID 512
#define CTX_ELEMS (B_SZ * S_LEN * HID)   // 8388608 floats

// Scratch (device globals: no allocation allowed)
__device__ float g_Q[CTX_ELEMS];
__device__ float g_K[CTX_ELEMS];
__device__ float g_V[CTX_ELEMS];
__device__ float g_Vt[CTX_ELEMS];        // V transposed: [B][H][S]

// Smem tile pitch (floats). 36 => bank = (36*r + c) % 32 = (4r + c) % 32,
// conflict-free for the frag-load pattern r in [0,8), c in [0,4).
#define PITCH 36
#define TILE_F (128 * PITCH)             // floats per 128x32 tile buffer
#define SMEM_BYTES (4 * TILE_F * 4)      // As0,As1,Bs0,Bs1 = 73728 B

// ---------------------------------------------------------------------------
// TF32 / cp.async helpers
// ---------------------------------------------------------------------------
__device__ __forceinline__ uint32_t f2tf32(float x) {
    uint32_t y;
    asm("cvt.rna.tf32.f32 %0, %1;" : "=r"(y) : "f"(x));
    return y;
}

__device__ __forceinline__ void mma_tf32(float d[4], const uint32_t a[4], const uint32_t b[2]) {
    asm volatile(
        "mma.sync.aligned.m16n8k8.row.col.f32.tf32.tf32.f32 "
        "{%0,%1,%2,%3}, {%4,%5,%6,%7}, {%8,%9}, {%0,%1,%2,%3};\n"
        : "+f"(d[0]), "+f"(d[1]), "+f"(d[2]), "+f"(d[3])
        : "r"(a[0]), "r"(a[1]), "r"(a[2]), "r"(a[3]),
          "r"(b[0]), "r"(b[1]));
}

__device__ __forceinline__ void cp16(float* smem_dst, const float* gsrc) {
    uint32_t s = (uint32_t)__cvta_generic_to_shared(smem_dst);
    asm volatile("cp.async.cg.shared.global [%0], [%1], 16;\n" :: "r"(s), "l"(gsrc));
}
#define CP_COMMIT() asm volatile("cp.async.commit_group;\n" ::: "memory")
#define CP_WAIT1()  asm volatile("cp.async.wait_group 1;\n" ::: "memory")
#define CP_WAIT0()  asm volatile("cp.async.wait_group 0;\n" ::: "memory")

// ---------------------------------------------------------------------------
// Shared GEMM tile compute: C(128x128) += A(128x32) * B(128x32)^T
// As/Bs hold raw fp32, layout [row][k] pitch PITCH; cvt to tf32 at frag load.
// 8 warps: wm in [0,4) (32 rows each), wn in [0,2) (64 cols each).
// ---------------------------------------------------------------------------
__device__ __forceinline__ void tile_mma(const float* As, const float* Bs,
                                         float acc[2][8][4], int lane, int wm, int wn) {
    const int g = lane >> 2;
    const int t = lane & 3;
#pragma unroll
    for (int kk = 0; kk < 32; kk += 8) {
        uint32_t a[2][4], b[8][2];
#pragma unroll
        for (int i = 0; i < 2; i++) {
            int r = wm * 32 + i * 16 + g;
            a[i][0] = f2tf32(As[r * PITCH + kk + t]);
            a[i][1] = f2tf32(As[(r + 8) * PITCH + kk + t]);
            a[i][2] = f2tf32(As[r * PITCH + kk + t + 4]);
            a[i][3] = f2tf32(As[(r + 8) * PITCH + kk + t + 4]);
        }
#pragma unroll
        for (int j = 0; j < 8; j++) {
            int n = wn * 64 + j * 8 + g;
            b[j][0] = f2tf32(Bs[n * PITCH + kk + t]);
            b[j][1] = f2tf32(Bs[n * PITCH + kk + t + 4]);
        }
#pragma unroll
        for (int i = 0; i < 2; i++)
#pragma unroll
            for (int j = 0; j < 8; j++)
                mma_tf32(acc[i][j], a[i], b[j]);
    }
}

// Async-load a 128x32 fp32 tile (row-major, K-contiguous, g at row0/col0).
// 256 threads, 4x cp.async(16B) each.
__device__ __forceinline__ void load_nt_async(float* S, const float* g, int ld, int tid) {
    int r = tid >> 3;           // 0..31
    int c = (tid & 7) * 4;      // 0,4,...,28
#pragma unroll
    for (int rr = 0; rr < 128; rr += 32)
        cp16(S + (r + rr) * PITCH + c, g + (size_t)(r + rr) * ld + c);
}

// Accumulator element coordinates inside the 128x128 CTA tile.
#define ACC_ROW(wm, i, lane, q) ((wm) * 32 + (i) * 16 + ((lane) >> 2) + (((q) >> 1) * 8))
#define ACC_COL(wn, j, lane, q) ((wn) * 64 + (j) * 8 + ((lane) & 3) * 2 + ((q) & 1))

#define ACC_INIT()                                 \
    float acc[2][8][4];                            \
    _Pragma("unroll") for (int i = 0; i < 2; i++)  \
    _Pragma("unroll") for (int j = 0; j < 8; j++)  \
    _Pragma("unroll") for (int q = 0; q < 4; q++) acc[i][j][q] = 0.f;

// ---------------------------------------------------------------------------
// Kernel 1: QKV projection.  out[m,o] = sum_h X[m,h] * W[o,h] + b[o]
// grid (4, 128, 3): z selects {Q,K,V}
// ---------------------------------------------------------------------------
__global__ __launch_bounds__(256) void proj_kernel(
    const float* __restrict__ Xq, const float* __restrict__ Xk, const float* __restrict__ Xv,
    const float* __restrict__ Wq, const float* __restrict__ bq,
    const float* __restrict__ Wk, const float* __restrict__ bk,
    const float* __restrict__ Wv, const float* __restrict__ bv) {
    extern __shared__ float sm[];
    float* As_[2] = {sm, sm + TILE_F};
    float* Bs_[2] = {sm + 2 * TILE_F, sm + 3 * TILE_F};

    const int mat = blockIdx.z;
    const float* X = (mat == 0) ? Xq : (mat == 1) ? Xk : Xv;
    const float* W = (mat == 0) ? Wq : (mat == 1) ? Wk : Wv;
    const float* bias = (mat == 0) ? bq : (mat == 1) ? bk : bv;
    float* out = (mat == 0) ? g_Q : (mat == 1) ? g_K : g_V;

    const int m0 = blockIdx.y * 128;
    const int n0 = blockIdx.x * 128;
    const int tid = threadIdx.x;
    const int lane = tid & 31;
    const int warp = tid >> 5;
    const int wm = warp & 3;
    const int wn = warp >> 2;

    ACC_INIT();

    const float* Ab = X + (size_t)m0 * HID;
    const float* Bb = W + (size_t)n0 * HID;
    const int ntiles = HID / 32;  // 16

    load_nt_async(As_[0], Ab, HID, tid);
    load_nt_async(Bs_[0], Bb, HID, tid);
    CP_COMMIT();

    for (int kt = 0; kt < ntiles; kt++) {
        const int cur = kt & 1, nxt = cur ^ 1;
        if (kt + 1 < ntiles) {
            load_nt_async(As_[nxt], Ab + (kt + 1) * 32, HID, tid);
            load_nt_async(Bs_[nxt], Bb + (kt + 1) * 32, HID, tid);
            CP_COMMIT();
            CP_WAIT1();
        } else {
            CP_WAIT0();
        }
        __syncthreads();
        tile_mma(As_[cur], Bs_[cur], acc, lane, wm, wn);
        __syncthreads();
    }

#pragma unroll
    for (int i = 0; i < 2; i++)
#pragma unroll
        for (int j = 0; j < 8; j++)
#pragma unroll
            for (int q = 0; q < 4; q++) {
                int rl = ACC_ROW(wm, i, lane, q);
                int cl = ACC_COL(wn, j, lane, q);
                out[(size_t)(m0 + rl) * HID + n0 + cl] = acc[i][j][q] + bias[n0 + cl];
            }
}

// ---------------------------------------------------------------------------
// Kernel 1b: V transpose.  g_Vt[b][h][s] = g_V[b][s][h]
// grid (S/32, H/32, B), block (32, 8). Smem tile, fully coalesced both sides.
// ---------------------------------------------------------------------------
__global__ __launch_bounds__(256) void transpose_v_kernel() {
    __shared__ float t[32][33];
    const int s0 = blockIdx.x * 32;
    const int h0 = blockIdx.y * 32;
    const int b = blockIdx.z;
    const int tx = threadIdx.x;
    const int ty = threadIdx.y;
    const float* src = g_V + (size_t)b * S_LEN * HID;
    float* dst = g_Vt + (size_t)b * S_LEN * HID;

#pragma unroll
    for (int j = 0; j < 32; j += 8)
        t[ty + j][tx] = src[(size_t)(s0 + ty + j) * HID + h0 + tx];
    __syncthreads();
#pragma unroll
    for (int j = 0; j < 32; j += 8)
        dst[(size_t)(h0 + ty + j) * S_LEN + s0 + tx] = t[tx][ty + j];
}

// ---------------------------------------------------------------------------
// Kernel 2: scores = scale * Q K^T, causal. Raw scores in the lower triangle,
// exact 0 above the diagonal (softmax of -1e7 underflows to exactly 0, and
// kernel 3 never reads cols > row).
// grid (32, 32, 4)
// ---------------------------------------------------------------------------
__global__ __launch_bounds__(256) void scores_kernel(float* __restrict__ wts) {
    extern __shared__ float sm[];
    float* As_[2] = {sm, sm + TILE_F};
    float* Bs_[2] = {sm + 2 * TILE_F, sm + 3 * TILE_F};

    const int b = blockIdx.z;
    const int m0 = blockIdx.y * 128;
    const int n0 = blockIdx.x * 128;
    const int tid = threadIdx.x;
    float* wb = wts + (size_t)b * S_LEN * S_LEN;

    if (n0 > m0) {  // strictly above diagonal: zero fill and exit
        float4 z = make_float4(0.f, 0.f, 0.f, 0.f);
        int rr = tid >> 5;            // 0..7
        int c4 = (tid & 31) * 4;      // 0..124
#pragma unroll
        for (int s = 0; s < 128; s += 8)
            *(float4*)(wb + (size_t)(m0 + rr + s) * S_LEN + n0 + c4) = z;
        return;
    }

    const int lane = tid & 31;
    const int warp = tid >> 5;
    const int wm = warp & 3;
    const int wn = warp >> 2;
    const float* Ab = g_Q + (size_t)b * S_LEN * HID + (size_t)m0 * HID;
    const float* Bb = g_K + (size_t)b * S_LEN * HID + (size_t)n0 * HID;

    ACC_INIT();

    const int ntiles = HID / 32;
    load_nt_async(As_[0], Ab, HID, tid);
    load_nt_async(Bs_[0], Bb, HID, tid);
    CP_COMMIT();

    for (int kt = 0; kt < ntiles; kt++) {
        const int cur = kt & 1, nxt = cur ^ 1;
        if (kt + 1 < ntiles) {
            load_nt_async(As_[nxt], Ab + (kt + 1) * 32, HID, tid);
            load_nt_async(Bs_[nxt], Bb + (kt + 1) * 32, HID, tid);
            CP_COMMIT();
            CP_WAIT1();
        } else {
            CP_WAIT0();
        }
        __syncthreads();
        tile_mma(As_[cur], Bs_[cur], acc, lane, wm, wn);
        __syncthreads();
    }

    const float scale = 0.04419417382415922f;  // 1/sqrt(512)
#pragma unroll
    for (int i = 0; i < 2; i++)
#pragma unroll
        for (int j = 0; j < 8; j++)
#pragma unroll
            for (int q = 0; q < 4; q++) {
                int rl = ACC_ROW(wm, i, lane, q);
                int cl = ACC_COL(wn, j, lane, q);
                float v = acc[i][j][q] * scale;
                if (n0 + cl > m0 + rl) v = 0.f;  // only bites on diagonal block
                wb[(size_t)(m0 + rl) * S_LEN + n0 + cl] = v;
            }
}

// ---------------------------------------------------------------------------
// Kernel 3: in-place row softmax over cols [0, row] only.
// One block (256 threads) per row; row staged entirely in smem.
// ---------------------------------------------------------------------------
__global__ __launch_bounds__(256) void softmax_kernel(float* __restrict__ wts) {
    __shared__ float buf[S_LEN];
    __shared__ float sred[8];
    __shared__ float sbc;

    const int row = blockIdx.x;
    const int r = row & (S_LEN - 1);
    const int n = r + 1;
    float* p = wts + (size_t)row * S_LEN;
    const int tid = threadIdx.x;

    float lm = -1e30f;
    for (int i = tid; i < n; i += 256) {
        float v = p[i];
        buf[i] = v;
        lm = fmaxf(lm, v);
    }
#pragma unroll
    for (int o = 16; o; o >>= 1) lm = fmaxf(lm, __shfl_xor_sync(0xffffffffu, lm, o));
    if ((tid & 31) == 0) sred[tid >> 5] = lm;
    __syncthreads();
    if (tid < 32) {
        float x = (tid < 8) ? sred[tid] : -1e30f;
#pragma unroll
        for (int o = 4; o; o >>= 1) x = fmaxf(x, __shfl_xor_sync(0xffffffffu, x, o));
        if (tid == 0) sbc = x;
    }
    __syncthreads();
    const float mx = sbc;

    float ls = 0.f;
    for (int i = tid; i < n; i += 256) {
        float e = __expf(buf[i] - mx);
        buf[i] = e;
        ls += e;
    }
#pragma unroll
    for (int o = 16; o; o >>= 1) ls += __shfl_xor_sync(0xffffffffu, ls, o);
    if ((tid & 31) == 0) sred[tid >> 5] = ls;
    __syncthreads();
    if (tid < 32) {
        float x = (tid < 8) ? sred[tid] : 0.f;
#pragma unroll
        for (int o = 4; o; o >>= 1) x += __shfl_xor_sync(0xffffffffu, x, o);
        if (tid == 0) sbc = x;
    }
    __syncthreads();
    const float inv = 1.0f / sbc;
    for (int i = tid; i < n; i += 256) p[i] = buf[i] * inv;
}

// ---------------------------------------------------------------------------
// Kernel 4: context = A V.  A has exact zeros above the diagonal, so no
// masking: just truncate the K loop at the diagonal block. V is consumed via
// g_Vt (H-major), so BOTH tiles are K-contiguous cp.async loads -> no smem
// transpose, no bank conflicts.
// grid (4, 32, 4): x = h-chunk (128 of 512), y = q-tile (reversed), z = batch
// ---------------------------------------------------------------------------
__global__ __launch_bounds__(256) void context_kernel(const float* __restrict__ wts,
                                                      float* __restrict__ ctx) {
    extern __shared__ float sm[];
    float* As_[2] = {sm, sm + TILE_F};
    float* Bs_[2] = {sm + 2 * TILE_F, sm + 3 * TILE_F};

    const int b = blockIdx.z;
    const int m0 = (31 - blockIdx.y) * 128;  // heavy tiles launch first
    const int h0 = blockIdx.x * 128;
    const int tid = threadIdx.x;
    const int lane = tid & 31;
    const int warp = tid >> 5;
    const int wm = warp & 3;
    const int wn = warp >> 2;

    const float* Ab = wts + (size_t)b * S_LEN * S_LEN + (size_t)m0 * S_LEN;
    const float* Bb = g_Vt + (size_t)b * S_LEN * HID + (size_t)h0 * S_LEN;

    ACC_INIT();

    const int ntiles = m0 / 32 + 4;  // only s <= m0+127 contributes

    load_nt_async(As_[0], Ab, S_LEN, tid);
    load_nt_async(Bs_[0], Bb, S_LEN, tid);
    CP_COMMIT();

    for (int kt = 0; kt < ntiles; kt++) {
        const int cur = kt & 1, nxt = cur ^ 1;
        if (kt + 1 < ntiles) {
            load_nt_async(As_[nxt], Ab + (kt + 1) * 32, S_LEN, tid);
            load_nt_async(Bs_[nxt], Bb + (kt + 1) * 32, S_LEN, tid);
            CP_COMMIT();
            CP_WAIT1();
        } else {
            CP_WAIT0();
        }
        __syncthreads();
        tile_mma(As_[cur], Bs_[cur], acc, lane, wm, wn);
        __syncthreads();
    }

#pragma unroll
    for (int i = 0; i < 2; i++)
#pragma unroll
        for (int j = 0; j < 8; j++)
#pragma unroll
            for (int q = 0; q < 4; q++) {
                int rl = ACC_ROW(wm, i, lane, q);
                int cl = ACC_COL(wn, j, lane, q);
                ctx[(size_t)(b * S_LEN + m0 + rl) * HID + h0 + cl] = acc[i][j][q];
            }
}

// ---------------------------------------------------------------------------
// Launch
// ---------------------------------------------------------------------------
extern "C" void kernel_launch(void* const* d_in, const int* in_sizes, int n_in,
                              void* d_out, int out_size) {
    const float* queries = (const float*)d_in[0];
    const float* keys    = (const float*)d_in[1];
    const float* values  = (const float*)d_in[2];
    const float* Wq      = (const float*)d_in[3];
    const float* bq      = (const float*)d_in[4];
    const float* Wk      = (const float*)d_in[5];
    const float* bk      = (const float*)d_in[6];
    const float* Wv      = (const float*)d_in[7];
    const float* bv      = (const float*)d_in[8];

    float* ctx = (float*)d_out;                 // (B, S, H)
    float* wts = (float*)d_out + CTX_ELEMS;     // (B, S, S)

    // Idempotent attribute sets (not stream ops; capture-safe).
    cudaFuncSetAttribute(proj_kernel,    cudaFuncAttributeMaxDynamicSharedMemorySize, SMEM_BYTES);
    cudaFuncSetAttribute(scores_kernel,  cudaFuncAttributeMaxDynamicSharedMemorySize, SMEM_BYTES);
    cudaFuncSetAttribute(context_kernel, cudaFuncAttributeMaxDynamicSharedMemorySize, SMEM_BYTES);

    proj_kernel<<<dim3(4, 128, 3), 256, SMEM_BYTES>>>(queries, keys, values, Wq, bq, Wk, bk, Wv, bv);
    transpose_v_kernel<<<dim3(S_LEN / 32, HID / 32, B_SZ), dim3(32, 8)>>>();
    scores_kernel<<<dim3(32, 32, 4), 256, SMEM_BYTES>>>(wts);
    softmax_kernel<<<B_SZ * S_LEN, 256>>>(wts);
    context_kernel<<<dim3(4, 32, 4), 256, SMEM_BYTES>>>(wts, ctx);
}